// round 3
// baseline (speedup 1.0000x reference)
#include <cuda_runtime.h>
#include <cstdint>

// Problem constants (fixed by dataset)
constexpr int NSRC0 = 200000;
constexpr int NDST0 = 50000;
constexpr int NDST1 = 10000;
constexpr int DIM   = 256;

// Static scratch (no allocation allowed)
__device__ float g_agg0[(size_t)NDST0 * DIM];
__device__ float g_h0  [(size_t)NDST0 * DIM];
__device__ float g_agg1[(size_t)NDST1 * DIM];
__device__ float g_h1  [(size_t)NDST1 * DIM];

// ---------------------------------------------------------------------------
// zero fill
// ---------------------------------------------------------------------------
__global__ void zero_kernel(float* __restrict__ p, int n_floats) {
    int i = blockIdx.x * blockDim.x + threadIdx.x;
    if (i * 4 < n_floats) {
        ((float4*)p)[i] = make_float4(0.f, 0.f, 0.f, 0.f);
    }
}

// ---------------------------------------------------------------------------
// scatter: agg[dst[e]] += tab[src[e]]  (256 floats/edge), one warp per edge,
// vector reduction red.global.add.v4.f32.
// ---------------------------------------------------------------------------
__global__ void __launch_bounds__(256) scatter_kernel(
    const float* __restrict__ tab,
    const int*   __restrict__ src,
    const int*   __restrict__ dst,
    float*       __restrict__ agg,
    int E)
{
    int warp = (blockIdx.x * blockDim.x + threadIdx.x) >> 5;
    int lane = threadIdx.x & 31;
    if (warp >= E) return;
    int s = __ldg(src + warp);
    int d = __ldg(dst + warp);
    const float4* srow = (const float4*)(tab + (size_t)s * DIM);
    float4*       drow = (float4*)(agg + (size_t)d * DIM);
    float4 v0 = __ldg(srow + lane);
    float4 v1 = __ldg(srow + lane + 32);
    float* a0 = (float*)(drow + lane);
    float* a1 = (float*)(drow + lane + 32);
    asm volatile("red.global.add.v4.f32 [%0], {%1,%2,%3,%4};"
                 :: "l"(a0), "f"(v0.x), "f"(v0.y), "f"(v0.z), "f"(v0.w) : "memory");
    asm volatile("red.global.add.v4.f32 [%0], {%1,%2,%3,%4};"
                 :: "l"(a1), "f"(v1.x), "f"(v1.y), "f"(v1.z), "f"(v1.w) : "memory");
}

// ---------------------------------------------------------------------------
// Double-buffered tiled fp32 GEMM:
//   Cout[row, colOff+col] = act( A_z[row,:K] @ B_z + bias? + Cin? )
// blockIdx.z selects block-diagonal slice via element offsets zA (A col), zB
// (B matrix), zC (output col). Register-staged double buffering, one sync per
// k-tile. Requires: N tile-aligned, K % BK == 0; M may be ragged.
// ---------------------------------------------------------------------------
template<int BM, int BN, int BK, int TM, int TN, bool ACC, bool RELU, bool HASBIAS>
__global__ void __launch_bounds__((BM / TM) * (BN / TN), 1) sgemm_kernel(
    int M, int K,
    const float* __restrict__ A, int lda, int zA,
    const float* __restrict__ B, int ldb, int zB,
    const float* __restrict__ bias,
    const float* __restrict__ Cin,
    float*       __restrict__ Cout, int ldc, int zC)
{
    constexpr int TX = BN / TN;
    constexpr int TY = BM / TM;
    constexpr int NT = TX * TY;
    constexpr int AV = (BM * BK / 4) / NT;   // float4 loads per thread (A)
    constexpr int BV = (BN * BK / 4) / NT;   // float4 loads per thread (B)

    __shared__ float As[2][BK][BM + 4];
    __shared__ float Bs[2][BK][BN + 4];

    const int tid = threadIdx.x;
    const int tx = tid % TX;
    const int ty = tid / TX;
    const int rowBase = blockIdx.y * BM;
    const int colBase = blockIdx.x * BN;
    const int colOff  = blockIdx.z * zC;

    A += (size_t)blockIdx.z * zA;
    B += (size_t)blockIdx.z * zB;

    float4 aReg[AV];
    float4 bReg[BV];

    auto ldgA = [&](int k0) {
#pragma unroll
        for (int l = 0; l < AV; l++) {
            int idx = tid + l * NT;
            int r = idx / (BK / 4);
            int c = idx % (BK / 4);
            int grow = rowBase + r;
            aReg[l] = (grow < M)
                ? *(const float4*)(A + (size_t)grow * lda + k0 + c * 4)
                : make_float4(0.f, 0.f, 0.f, 0.f);
        }
    };
    auto ldgB = [&](int k0) {
#pragma unroll
        for (int l = 0; l < BV; l++) {
            int idx = tid + l * NT;
            int kr = idx / (BN / 4);
            int c  = idx % (BN / 4);
            bReg[l] = *(const float4*)(B + (size_t)(k0 + kr) * ldb + colBase + c * 4);
        }
    };
    auto stsA = [&](int buf) {
#pragma unroll
        for (int l = 0; l < AV; l++) {
            int idx = tid + l * NT;
            int r = idx / (BK / 4);
            int c = idx % (BK / 4);
            As[buf][c * 4 + 0][r] = aReg[l].x;
            As[buf][c * 4 + 1][r] = aReg[l].y;
            As[buf][c * 4 + 2][r] = aReg[l].z;
            As[buf][c * 4 + 3][r] = aReg[l].w;
        }
    };
    auto stsB = [&](int buf) {
#pragma unroll
        for (int l = 0; l < BV; l++) {
            int idx = tid + l * NT;
            int kr = idx / (BN / 4);
            int c  = idx % (BN / 4);
            *(float4*)&Bs[buf][kr][c * 4] = bReg[l];
        }
    };

    float acc[TM][TN];
#pragma unroll
    for (int i = 0; i < TM; i++)
#pragma unroll
        for (int j = 0; j < TN; j++) acc[i][j] = 0.f;

    const int KT = K / BK;
    ldgA(0); ldgB(0);
    stsA(0); stsB(0);
    __syncthreads();

    for (int kt = 0; kt < KT; kt++) {
        const int cur = kt & 1;
        const int nxt = cur ^ 1;
        if (kt + 1 < KT) { ldgA((kt + 1) * BK); ldgB((kt + 1) * BK); }

#pragma unroll
        for (int k = 0; k < BK; k++) {
            float af[TM], bf[TN];
#pragma unroll
            for (int i = 0; i < TM; i += 4) {
                float4 t = *(const float4*)&As[cur][k][ty * TM + i];
                af[i] = t.x; af[i + 1] = t.y; af[i + 2] = t.z; af[i + 3] = t.w;
            }
#pragma unroll
            for (int j = 0; j < TN; j += 4) {
                float4 t = *(const float4*)&Bs[cur][k][tx * TN + j];
                bf[j] = t.x; bf[j + 1] = t.y; bf[j + 2] = t.z; bf[j + 3] = t.w;
            }
#pragma unroll
            for (int i = 0; i < TM; i++)
#pragma unroll
                for (int j = 0; j < TN; j++)
                    acc[i][j] = fmaf(af[i], bf[j], acc[i][j]);
        }

        if (kt + 1 < KT) { stsA(nxt); stsB(nxt); }
        __syncthreads();
    }

#pragma unroll
    for (int i = 0; i < TM; i++) {
        int row = rowBase + ty * TM + i;
        if (row < M) {
#pragma unroll
            for (int j = 0; j < TN; j += 4) {
                int col = colOff + colBase + tx * TN + j;
                float4 v = make_float4(acc[i][j], acc[i][j + 1], acc[i][j + 2], acc[i][j + 3]);
                if constexpr (HASBIAS) {
                    float4 bv = *(const float4*)(bias + col);
                    v.x += bv.x; v.y += bv.y; v.z += bv.z; v.w += bv.w;
                }
                if constexpr (ACC) {
                    float4 cv = *(const float4*)(Cin + (size_t)row * ldc + col);
                    v.x += cv.x; v.y += cv.y; v.z += cv.z; v.w += cv.w;
                }
                if constexpr (RELU) {
                    v.x = fmaxf(v.x, 0.f); v.y = fmaxf(v.y, 0.f);
                    v.z = fmaxf(v.z, 0.f); v.w = fmaxf(v.w, 0.f);
                }
                *(float4*)(Cout + (size_t)row * ldc + col) = v;
            }
        }
    }
}

// ---------------------------------------------------------------------------
// Link prediction head: out[g] = relu((h[s]*h[d]) @ pw1 + pb1) @ pw2 + pb2
// ---------------------------------------------------------------------------
__global__ void __launch_bounds__(128) pred_kernel(
    const float* __restrict__ h,
    const int*   __restrict__ ps, const int* __restrict__ pd,
    const int*   __restrict__ ns, const int* __restrict__ nd,
    const float* __restrict__ pw1, const float* __restrict__ pb1,
    const float* __restrict__ pw2, const float* __restrict__ pb2,
    float*       __restrict__ out, int npair)
{
    constexpr int P = 16;
    __shared__ float e[P][DIM];
    __shared__ float sred[P][4];

    int tid = threadIdx.x;
    int base = blockIdx.x * P;

#pragma unroll
    for (int p = 0; p < P; p++) {
        if (tid < 64) {
            int g = base + p;
            int s, d;
            if (g < npair) { s = __ldg(ps + g);         d = __ldg(pd + g); }
            else           { s = __ldg(ns + g - npair); d = __ldg(nd + g - npair); }
            const float4* hs = (const float4*)(h + (size_t)s * DIM);
            const float4* hd = (const float4*)(h + (size_t)d * DIM);
            float4 a = __ldg(hs + tid);
            float4 b = __ldg(hd + tid);
            *(float4*)&e[p][tid * 4] = make_float4(a.x * b.x, a.y * b.y, a.z * b.z, a.w * b.w);
        }
    }
    __syncthreads();

    float accp[P];
#pragma unroll
    for (int p = 0; p < P; p++) accp[p] = 0.f;

    for (int i = 0; i < DIM; i++) {
        float w = __ldg(pw1 + i * 128 + tid);
#pragma unroll
        for (int p = 0; p < P; p++) accp[p] = fmaf(e[p][i], w, accp[p]);
    }

    float w2  = __ldg(pw2 + tid);
    float b1v = __ldg(pb1 + tid);
    int lane = tid & 31;
    int wid  = tid >> 5;
#pragma unroll
    for (int p = 0; p < P; p++) {
        float z = fmaxf(accp[p] + b1v, 0.f) * w2;
#pragma unroll
        for (int o = 16; o > 0; o >>= 1) z += __shfl_down_sync(0xffffffffu, z, o);
        if (lane == 0) sred[p][wid] = z;
    }
    __syncthreads();
    if (tid < P) {
        out[base + tid] = sred[tid][0] + sred[tid][1] + sred[tid][2] + sred[tid][3] + pb2[0];
    }
}

// ---------------------------------------------------------------------------
// launch
// ---------------------------------------------------------------------------
extern "C" void kernel_launch(void* const* d_in, const int* in_sizes, int n_in,
                              void* d_out, int out_size)
{
    const float* x     = (const float*)d_in[0];
    const int* src0    = (const int*)d_in[1];
    const int* dst0    = (const int*)d_in[2];
    const int* src1    = (const int*)d_in[3];
    const int* dst1    = (const int*)d_in[4];
    const int* pos_src = (const int*)d_in[5];
    const int* pos_dst = (const int*)d_in[6];
    const int* neg_src = (const int*)d_in[7];
    const int* neg_dst = (const int*)d_in[8];
    const float* W0    = (const float*)d_in[9];
    const float* loop0 = (const float*)d_in[10];
    const float* b0    = (const float*)d_in[11];
    const float* W1    = (const float*)d_in[12];
    const float* loop1 = (const float*)d_in[13];
    const float* b1    = (const float*)d_in[14];
    const float* pw1   = (const float*)d_in[15];
    const float* pb1   = (const float*)d_in[16];
    const float* pw2   = (const float*)d_in[17];
    const float* pb2   = (const float*)d_in[18];

    const int E0 = in_sizes[1];
    const int E1 = in_sizes[3];
    const int NP = in_sizes[5];

    float *agg0, *h0, *agg1, *h1;
    cudaGetSymbolAddress((void**)&agg0, g_agg0);
    cudaGetSymbolAddress((void**)&h0,   g_h0);
    cudaGetSymbolAddress((void**)&agg1, g_agg1);
    cudaGetSymbolAddress((void**)&h1,   g_h1);

    float* out   = (float*)d_out;
    float* out_h = out + 2 * NP;   // [10000, 256] final embeddings

    // zero accumulators
    zero_kernel<<<(NDST0 * DIM / 4 + 255) / 256, 256>>>(agg0, NDST0 * DIM);
    zero_kernel<<<(NDST1 * DIM / 4 + 255) / 256, 256>>>(agg1, NDST1 * DIM);

    // layer 0: scatter raw x (linearity: transform after aggregation)
    scatter_kernel<<<(E0 + 7) / 8, 256>>>(x, src0, dst0, agg0, E0);

    // h0_pre = x[:50000] @ loop0 + b0
    {
        dim3 grid(DIM / 128, (NDST0 + 127) / 128, 1);
        sgemm_kernel<128, 128, 16, 8, 8, false, false, true><<<grid, 256>>>(
            NDST0, DIM, x, DIM, 0, loop0, DIM, 0, b0, nullptr, h0, DIM, 0);
    }
    // h0 = relu( bdd(agg0, W0) + h0_pre )
    {
        dim3 grid(1, (NDST0 + 127) / 128, 4);
        sgemm_kernel<128, 64, 16, 8, 4, true, true, false><<<grid, 256>>>(
            NDST0, 64, agg0, DIM, 64, W0, 64, 64 * 64, nullptr, h0, h0, DIM, 64);
    }

    // layer 1
    scatter_kernel<<<(E1 + 7) / 8, 256>>>(h0, src1, dst1, agg1, E1);
    {
        dim3 grid(DIM / 128, (NDST1 + 127) / 128, 1);
        sgemm_kernel<128, 128, 16, 8, 8, false, false, true><<<grid, 256>>>(
            NDST1, DIM, h0, DIM, 0, loop1, DIM, 0, b1, nullptr, h1, DIM, 0);
    }
    {
        dim3 grid(1, (NDST1 + 127) / 128, 4);
        sgemm_kernel<128, 64, 16, 8, 4, true, true, false><<<grid, 256>>>(
            NDST1, 64, agg1, DIM, 64, W1, 64, 64 * 64, nullptr, h1, out_h, DIM, 64);
    }

    // prediction head: 10000 pairs -> out[0:10000]
    pred_kernel<<<(2 * NP) / 16, 128>>>(out_h, pos_src, pos_dst, neg_src, neg_dst,
                                        pw1, pb1, pw2, pb2, out, NP);
}

// round 6
// speedup vs baseline: 1.0955x; 1.0955x over previous
#include <cuda_runtime.h>
#include <cstdint>

// Problem constants (fixed by dataset)
constexpr int NSRC0 = 200000;
constexpr int NDST0 = 50000;
constexpr int NDST1 = 10000;
constexpr int DIM   = 256;
constexpr int E0MAX = 800000;
constexpr int E1MAX = 160000;

// Static scratch (no allocation allowed)
__device__ float g_agg0[(size_t)NDST0 * DIM];
__device__ float g_h0  [(size_t)NDST0 * DIM];
__device__ float g_agg1[(size_t)NDST1 * DIM];
__device__ float g_h1  [(size_t)NDST1 * DIM];

// CSR scratch
__device__ int g_deg0[NDST0];
__device__ int g_cur0[NDST0];
__device__ int g_row0[NDST0 + 1];
__device__ int g_eidx0[E0MAX];
__device__ int g_deg1[NDST1];
__device__ int g_cur1[NDST1];
__device__ int g_row1[NDST1 + 1];
__device__ int g_eidx1[E1MAX];

// ---------------------------------------------------------------------------
// cp.async helpers
// ---------------------------------------------------------------------------
__device__ __forceinline__ void cp_async16(uint32_t smem_addr, const void* gptr, int src_bytes) {
    asm volatile("cp.async.ca.shared.global [%0], [%1], 16, %2;\n"
                 :: "r"(smem_addr), "l"(gptr), "r"(src_bytes));
}
__device__ __forceinline__ void cp_commit() {
    asm volatile("cp.async.commit_group;\n" ::: "memory");
}
template<int N>
__device__ __forceinline__ void cp_wait() {
    asm volatile("cp.async.wait_group %0;\n" :: "n"(N) : "memory");
}

// ---------------------------------------------------------------------------
// zero fill (16B granules; n_bytes must be multiple of 16)
// ---------------------------------------------------------------------------
__global__ void zero16_kernel(void* __restrict__ p, int n_16b) {
    int i = blockIdx.x * blockDim.x + threadIdx.x;
    if (i < n_16b) ((float4*)p)[i] = make_float4(0.f, 0.f, 0.f, 0.f);
}

// ---------------------------------------------------------------------------
// CSR build: histogram, one-block scan, placement
// ---------------------------------------------------------------------------
__global__ void hist_kernel(const int* __restrict__ dst, int* __restrict__ deg, int E) {
    int i = blockIdx.x * blockDim.x + threadIdx.x;
    if (i < E) atomicAdd(deg + __ldg(dst + i), 1);
}

// exclusive scan of deg[0..n) into row[0..n]; single block of 1024 threads
__global__ void __launch_bounds__(1024) scan_kernel(const int* __restrict__ deg,
                                                    int* __restrict__ row, int n) {
    __shared__ int part[1024];
    int tid = threadIdx.x;
    int chunk = (n + 1023) / 1024;
    int begin = tid * chunk;
    int end   = begin + chunk < n ? begin + chunk : n;
    if (begin > n) begin = n;
    int sum = 0;
    for (int i = begin; i < end; i++) sum += deg[i];
    part[tid] = sum;
    __syncthreads();
    for (int off = 1; off < 1024; off <<= 1) {
        int v = (tid >= off) ? part[tid - off] : 0;
        __syncthreads();
        part[tid] += v;
        __syncthreads();
    }
    int run = (tid == 0) ? 0 : part[tid - 1];
    for (int i = begin; i < end; i++) { row[i] = run; run += deg[i]; }
    if (end == n) row[n] = run;   // idempotent: all qualifying threads write total
}

__global__ void place_kernel(const int* __restrict__ src, const int* __restrict__ dst,
                             const int* __restrict__ row, int* __restrict__ cur,
                             int* __restrict__ eidx, int E) {
    int i = blockIdx.x * blockDim.x + threadIdx.x;
    if (i < E) {
        int d = __ldg(dst + i);
        int p = atomicAdd(cur + d, 1);
        eidx[__ldg(row + d) + p] = __ldg(src + i);
    }
}

// ---------------------------------------------------------------------------
// gather-sum: one warp per dst row; agg[row] = sum_{e in row} tab[eidx[e]]
// Plain stores — no float atomics, no pre-zeroing needed.
// ---------------------------------------------------------------------------
__global__ void __launch_bounds__(256) gather_sum_kernel(
    const float* __restrict__ tab,
    const int*   __restrict__ eidx,
    const int*   __restrict__ row,
    float*       __restrict__ agg,
    int nrows)
{
    int r = (blockIdx.x * blockDim.x + threadIdx.x) >> 5;
    int lane = threadIdx.x & 31;
    if (r >= nrows) return;
    int e0 = __ldg(row + r);
    int e1 = __ldg(row + r + 1);
    float4 acc0 = make_float4(0.f, 0.f, 0.f, 0.f);
    float4 acc1 = make_float4(0.f, 0.f, 0.f, 0.f);
    for (int e = e0; e < e1; e++) {
        int s = __ldg(eidx + e);
        const float4* p = (const float4*)(tab + (size_t)s * DIM);
        float4 v0 = __ldg(p + lane);
        float4 v1 = __ldg(p + lane + 32);
        acc0.x += v0.x; acc0.y += v0.y; acc0.z += v0.z; acc0.w += v0.w;
        acc1.x += v1.x; acc1.y += v1.y; acc1.z += v1.z; acc1.w += v1.w;
    }
    float4* o = (float4*)(agg + (size_t)r * DIM);
    o[lane]      = acc0;
    o[lane + 32] = acc1;
}

// ---------------------------------------------------------------------------
// cp.async double-buffered tiled fp32 GEMM:
//   Cout[row, colOff+col] = act( A_z[row,:K] @ B_z + bias? + Cin? )
// A tile untransposed (As[m][k]); inner loop reads A as float4 along K.
// No register staging -> 2 CTAs/SM. blockIdx.z selects block-diag slice.
// Requires: N tile-aligned, K % BK == 0; M may be ragged.
// ---------------------------------------------------------------------------
template<int BM, int BN, int BK, int TM, int TN, bool ACC, bool RELU, bool HASBIAS>
__global__ void __launch_bounds__((BM / TM) * (BN / TN), 2) sgemm_kernel(
    int M, int K,
    const float* __restrict__ A, int lda, int zA,
    const float* __restrict__ B, int ldb, int zB,
    const float* __restrict__ bias,
    const float* __restrict__ Cin,
    float*       __restrict__ Cout, int ldc, int zC)
{
    constexpr int TX = BN / TN;
    constexpr int TY = BM / TM;
    constexpr int NT = TX * TY;
    constexpr int AV = (BM * BK / 4) / NT;
    constexpr int BV = (BN * BK / 4) / NT;
    static_assert(AV >= 1 && BV >= 1, "tile too small");

    __shared__ float As[2][BM][BK + 4];
    __shared__ float Bs[2][BK][BN + 4];

    const int tid = threadIdx.x;
    const int tx = tid % TX;
    const int ty = tid / TX;
    const int rowBase = blockIdx.y * BM;
    const int colBase = blockIdx.x * BN;
    const int colOff  = blockIdx.z * zC;

    A += (size_t)blockIdx.z * zA;
    B += (size_t)blockIdx.z * zB;

    auto loadTile = [&](int k0, int buf) {
#pragma unroll
        for (int l = 0; l < AV; l++) {
            int idx = tid + l * NT;
            int r = idx / (BK / 4);
            int c = idx % (BK / 4);
            int grow = rowBase + r;
            int ok = (grow < M) ? 16 : 0;
            int gclamp = (grow < M) ? grow : (M - 1);
            uint32_t sa = (uint32_t)__cvta_generic_to_shared(&As[buf][r][c * 4]);
            cp_async16(sa, A + (size_t)gclamp * lda + k0 + c * 4, ok);
        }
#pragma unroll
        for (int l = 0; l < BV; l++) {
            int idx = tid + l * NT;
            int kr = idx / (BN / 4);
            int c  = idx % (BN / 4);
            uint32_t sb = (uint32_t)__cvta_generic_to_shared(&Bs[buf][kr][c * 4]);
            cp_async16(sb, B + (size_t)(k0 + kr) * ldb + colBase + c * 4, 16);
        }
    };

    float acc[TM][TN];
#pragma unroll
    for (int i = 0; i < TM; i++)
#pragma unroll
        for (int j = 0; j < TN; j++) acc[i][j] = 0.f;

    const int KT = K / BK;
    loadTile(0, 0);
    cp_commit();

    for (int kt = 0; kt < KT; kt++) {
        const int cur = kt & 1;
        const int nxt = cur ^ 1;
        if (kt + 1 < KT) {
            loadTile((kt + 1) * BK, nxt);
            cp_commit();
            cp_wait<1>();
        } else {
            cp_wait<0>();
        }
        __syncthreads();

#pragma unroll
        for (int kg = 0; kg < BK; kg += 4) {
            float4 a4[TM];
#pragma unroll
            for (int i = 0; i < TM; i++)
                a4[i] = *(const float4*)&As[cur][ty * TM + i][kg];
#pragma unroll
            for (int kk = 0; kk < 4; kk++) {
                float bf[TN];
#pragma unroll
                for (int j = 0; j < TN; j += 4) {
                    float4 t = *(const float4*)&Bs[cur][kg + kk][tx * TN + j];
                    bf[j] = t.x; bf[j + 1] = t.y; bf[j + 2] = t.z; bf[j + 3] = t.w;
                }
#pragma unroll
                for (int i = 0; i < TM; i++) {
                    float a = (kk == 0) ? a4[i].x : (kk == 1) ? a4[i].y
                             : (kk == 2) ? a4[i].z : a4[i].w;
#pragma unroll
                    for (int j = 0; j < TN; j++)
                        acc[i][j] = fmaf(a, bf[j], acc[i][j]);
                }
            }
        }
        __syncthreads();
    }

#pragma unroll
    for (int i = 0; i < TM; i++) {
        int row = rowBase + ty * TM + i;
        if (row < M) {
#pragma unroll
            for (int j = 0; j < TN; j += 4) {
                int col = colOff + colBase + tx * TN + j;
                float4 v = make_float4(acc[i][j], acc[i][j + 1], acc[i][j + 2], acc[i][j + 3]);
                if constexpr (HASBIAS) {
                    float4 bv = *(const float4*)(bias + col);
                    v.x += bv.x; v.y += bv.y; v.z += bv.z; v.w += bv.w;
                }
                if constexpr (ACC) {
                    float4 cv = *(const float4*)(Cin + (size_t)row * ldc + col);
                    v.x += cv.x; v.y += cv.y; v.z += cv.z; v.w += cv.w;
                }
                if constexpr (RELU) {
                    v.x = fmaxf(v.x, 0.f); v.y = fmaxf(v.y, 0.f);
                    v.z = fmaxf(v.z, 0.f); v.w = fmaxf(v.w, 0.f);
                }
                *(float4*)(Cout + (size_t)row * ldc + col) = v;
            }
        }
    }
}

// ---------------------------------------------------------------------------
// Link prediction head: out[g] = relu((h[s]*h[d]) @ pw1 + pb1) @ pw2 + pb2
// ---------------------------------------------------------------------------
__global__ void __launch_bounds__(128) pred_kernel(
    const float* __restrict__ h,
    const int*   __restrict__ ps, const int* __restrict__ pd,
    const int*   __restrict__ ns, const int* __restrict__ nd,
    const float* __restrict__ pw1, const float* __restrict__ pb1,
    const float* __restrict__ pw2, const float* __restrict__ pb2,
    float*       __restrict__ out, int npair)
{
    constexpr int P = 16;
    __shared__ float e[P][DIM];
    __shared__ float sred[P][4];

    int tid = threadIdx.x;
    int base = blockIdx.x * P;

#pragma unroll
    for (int p = 0; p < P; p++) {
        if (tid < 64) {
            int g = base + p;
            int s, d;
            if (g < npair) { s = __ldg(ps + g);         d = __ldg(pd + g); }
            else           { s = __ldg(ns + g - npair); d = __ldg(nd + g - npair); }
            const float4* hs = (const float4*)(h + (size_t)s * DIM);
            const float4* hd = (const float4*)(h + (size_t)d * DIM);
            float4 a = __ldg(hs + tid);
            float4 b = __ldg(hd + tid);
            *(float4*)&e[p][tid * 4] = make_float4(a.x * b.x, a.y * b.y, a.z * b.z, a.w * b.w);
        }
    }
    __syncthreads();

    float accp[P];
#pragma unroll
    for (int p = 0; p < P; p++) accp[p] = 0.f;

    for (int i = 0; i < DIM; i++) {
        float w = __ldg(pw1 + i * 128 + tid);
#pragma unroll
        for (int p = 0; p < P; p++) accp[p] = fmaf(e[p][i], w, accp[p]);
    }

    float w2  = __ldg(pw2 + tid);
    float b1v = __ldg(pb1 + tid);
    int lane = tid & 31;
    int wid  = tid >> 5;
#pragma unroll
    for (int p = 0; p < P; p++) {
        float z = fmaxf(accp[p] + b1v, 0.f) * w2;
#pragma unroll
        for (int o = 16; o > 0; o >>= 1) z += __shfl_down_sync(0xffffffffu, z, o);
        if (lane == 0) sred[p][wid] = z;
    }
    __syncthreads();
    if (tid < P) {
        out[base + tid] = sred[tid][0] + sred[tid][1] + sred[tid][2] + sred[tid][3] + pb2[0];
    }
}

// ---------------------------------------------------------------------------
// launch
// ---------------------------------------------------------------------------
extern "C" void kernel_launch(void* const* d_in, const int* in_sizes, int n_in,
                              void* d_out, int out_size)
{
    const float* x     = (const float*)d_in[0];
    const int* src0    = (const int*)d_in[1];
    const int* dst0    = (const int*)d_in[2];
    const int* src1    = (const int*)d_in[3];
    const int* dst1    = (const int*)d_in[4];
    const int* pos_src = (const int*)d_in[5];
    const int* pos_dst = (const int*)d_in[6];
    const int* neg_src = (const int*)d_in[7];
    const int* neg_dst = (const int*)d_in[8];
    const float* W0    = (const float*)d_in[9];
    const float* loop0 = (const float*)d_in[10];
    const float* b0    = (const float*)d_in[11];
    const float* W1    = (const float*)d_in[12];
    const float* loop1 = (const float*)d_in[13];
    const float* b1    = (const float*)d_in[14];
    const float* pw1   = (const float*)d_in[15];
    const float* pb1   = (const float*)d_in[16];
    const float* pw2   = (const float*)d_in[17];
    const float* pb2   = (const float*)d_in[18];

    const int E0 = in_sizes[1];
    const int E1 = in_sizes[3];
    const int NP = in_sizes[5];

    float *agg0, *h0, *agg1, *h1;
    cudaGetSymbolAddress((void**)&agg0, g_agg0);
    cudaGetSymbolAddress((void**)&h0,   g_h0);
    cudaGetSymbolAddress((void**)&agg1, g_agg1);
    cudaGetSymbolAddress((void**)&h1,   g_h1);
    int *deg0, *cur0, *row0, *eidx0, *deg1, *cur1, *row1, *eidx1;
    cudaGetSymbolAddress((void**)&deg0,  g_deg0);
    cudaGetSymbolAddress((void**)&cur0,  g_cur0);
    cudaGetSymbolAddress((void**)&row0,  g_row0);
    cudaGetSymbolAddress((void**)&eidx0, g_eidx0);
    cudaGetSymbolAddress((void**)&deg1,  g_deg1);
    cudaGetSymbolAddress((void**)&cur1,  g_cur1);
    cudaGetSymbolAddress((void**)&row1,  g_row1);
    cudaGetSymbolAddress((void**)&eidx1, g_eidx1);

    float* out   = (float*)d_out;
    float* out_h = out + 2 * NP;   // [10000, 256] final embeddings

    // ---------------- layer 0 ----------------
    // CSR build (deg/cur sizes are multiples of 4 ints = 16B granules)
    zero16_kernel<<<(NDST0 / 4 + 255) / 256, 256>>>(deg0, NDST0 / 4);
    zero16_kernel<<<(NDST0 / 4 + 255) / 256, 256>>>(cur0, NDST0 / 4);
    hist_kernel<<<(E0 + 255) / 256, 256>>>(dst0, deg0, E0);
    scan_kernel<<<1, 1024>>>(deg0, row0, NDST0);
    place_kernel<<<(E0 + 255) / 256, 256>>>(src0, dst0, row0, cur0, eidx0, E0);
    // agg0 = segment_sum(x[src0], dst0) via gather (no float atomics)
    gather_sum_kernel<<<(NDST0 * 32 + 255) / 256, 256>>>(x, eidx0, row0, agg0, NDST0);

    // h0_pre = x[:50000] @ loop0 + b0
    {
        dim3 grid(DIM / 128, (NDST0 + 127) / 128, 1);
        sgemm_kernel<128, 128, 16, 8, 8, false, false, true><<<grid, 256>>>(
            NDST0, DIM, x, DIM, 0, loop0, DIM, 0, b0, nullptr, h0, DIM, 0);
    }
    // h0 = relu( bdd(agg0, W0) + h0_pre )
    {
        dim3 grid(1, (NDST0 + 127) / 128, 4);
        sgemm_kernel<128, 64, 16, 8, 4, true, true, false><<<grid, 256>>>(
            NDST0, 64, agg0, DIM, 64, W0, 64, 64 * 64, nullptr, h0, h0, DIM, 64);
    }

    // ---------------- layer 1 ----------------
    zero16_kernel<<<(NDST1 / 4 + 255) / 256, 256>>>(deg1, NDST1 / 4);
    zero16_kernel<<<(NDST1 / 4 + 255) / 256, 256>>>(cur1, NDST1 / 4);
    hist_kernel<<<(E1 + 255) / 256, 256>>>(dst1, deg1, E1);
    scan_kernel<<<1, 1024>>>(deg1, row1, NDST1);
    place_kernel<<<(E1 + 255) / 256, 256>>>(src1, dst1, row1, cur1, eidx1, E1);
    gather_sum_kernel<<<(NDST1 * 32 + 255) / 256, 256>>>(h0, eidx1, row1, agg1, NDST1);

    {
        dim3 grid(DIM / 128, (NDST1 + 127) / 128, 1);
        sgemm_kernel<128, 128, 16, 8, 8, false, false, true><<<grid, 256>>>(
            NDST1, DIM, h0, DIM, 0, loop1, DIM, 0, b1, nullptr, h1, DIM, 0);
    }
    {
        dim3 grid(1, (NDST1 + 127) / 128, 4);
        sgemm_kernel<128, 64, 16, 8, 4, true, true, false><<<grid, 256>>>(
            NDST1, 64, agg1, DIM, 64, W1, 64, 64 * 64, nullptr, h1, out_h, DIM, 64);
    }

    // prediction head: 10000 pairs -> out[0:10000]
    pred_kernel<<<(2 * NP) / 16, 128>>>(out_h, pos_src, pos_dst, neg_src, neg_dst,
                                        pw1, pb1, pw2, pb2, out, NP);
}

// round 7
// speedup vs baseline: 1.1473x; 1.0473x over previous
#include <cuda_runtime.h>
#include <cstdint>

// Problem constants (fixed by dataset)
constexpr int NSRC0 = 200000;
constexpr int NDST0 = 50000;
constexpr int NDST1 = 10000;
constexpr int DIM   = 256;
constexpr int E0MAX = 800000;
constexpr int E1MAX = 160000;

// Static scratch (no allocation allowed)
__device__ float g_agg0[(size_t)NDST0 * DIM];
__device__ float g_h0  [(size_t)NDST0 * DIM];
__device__ float g_agg1[(size_t)NDST1 * DIM];
__device__ float g_h1  [(size_t)NDST1 * DIM];

// CSR scratch
__device__ int g_deg0[NDST0];
__device__ int g_cur0[NDST0];
__device__ int g_row0[NDST0 + 1];
__device__ int g_eidx0[E0MAX];
__device__ int g_deg1[NDST1];
__device__ int g_cur1[NDST1];
__device__ int g_row1[NDST1 + 1];
__device__ int g_eidx1[E1MAX];
__device__ int g_bsum[256];
__device__ int g_boff[257];

// ---------------------------------------------------------------------------
// cp.async helpers
// ---------------------------------------------------------------------------
__device__ __forceinline__ void cp_async16(uint32_t smem_addr, const void* gptr, int src_bytes) {
    asm volatile("cp.async.ca.shared.global [%0], [%1], 16, %2;\n"
                 :: "r"(smem_addr), "l"(gptr), "r"(src_bytes));
}
__device__ __forceinline__ void cp_commit() {
    asm volatile("cp.async.commit_group;\n" ::: "memory");
}
template<int N>
__device__ __forceinline__ void cp_wait() {
    asm volatile("cp.async.wait_group %0;\n" :: "n"(N) : "memory");
}

// ---------------------------------------------------------------------------
// zero fill (16B granules)
// ---------------------------------------------------------------------------
__global__ void zero16_kernel(void* __restrict__ p, int n_16b) {
    int i = blockIdx.x * blockDim.x + threadIdx.x;
    if (i < n_16b) ((float4*)p)[i] = make_float4(0.f, 0.f, 0.f, 0.f);
}

// ---------------------------------------------------------------------------
// CSR build: histogram, hierarchical coalesced scan, placement
// ---------------------------------------------------------------------------
__global__ void hist_kernel(const int* __restrict__ dst, int* __restrict__ deg, int E) {
    int i = blockIdx.x * blockDim.x + threadIdx.x;
    if (i < E) atomicAdd(deg + __ldg(dst + i), 1);
}

// per-block exclusive scan (1024 elems/block, coalesced, shfl-based)
__global__ void __launch_bounds__(1024) block_scan_kernel(
    const int* __restrict__ deg, int* __restrict__ row,
    int* __restrict__ bsum, int n)
{
    __shared__ int wsum[32];
    int tid = threadIdx.x;
    int i = blockIdx.x * 1024 + tid;
    int v = (i < n) ? deg[i] : 0;
    int lane = tid & 31, wid = tid >> 5;
    int s = v;
#pragma unroll
    for (int o = 1; o < 32; o <<= 1) {
        int t = __shfl_up_sync(0xffffffffu, s, o);
        if (lane >= o) s += t;
    }
    if (lane == 31) wsum[wid] = s;
    __syncthreads();
    if (wid == 0) {
        int ws = wsum[lane];
#pragma unroll
        for (int o = 1; o < 32; o <<= 1) {
            int t = __shfl_up_sync(0xffffffffu, ws, o);
            if (lane >= o) ws += t;
        }
        wsum[lane] = ws;
    }
    __syncthreads();
    int excl = s - v + (wid > 0 ? wsum[wid - 1] : 0);
    if (i < n) row[i] = excl;
    if (tid == 0) bsum[blockIdx.x] = wsum[31];
}

// scan the (<=256) block sums; boff[nb] = grand total
__global__ void bsum_scan_kernel(const int* __restrict__ bsum,
                                 int* __restrict__ boff, int nb) {
    if (threadIdx.x == 0) {
        int run = 0;
        for (int b = 0; b < nb; b++) { boff[b] = run; run += bsum[b]; }
        boff[nb] = run;
    }
}

__global__ void add_off_kernel(int* __restrict__ row, const int* __restrict__ boff,
                               int n, int nb) {
    int i = blockIdx.x * blockDim.x + threadIdx.x;
    if (i < n) row[i] += __ldg(boff + (i >> 10));
    if (i == 0) row[n] = __ldg(boff + nb);
}

__global__ void place_kernel(const int* __restrict__ src, const int* __restrict__ dst,
                             const int* __restrict__ row, int* __restrict__ cur,
                             int* __restrict__ eidx, int E) {
    int i = blockIdx.x * blockDim.x + threadIdx.x;
    if (i < E) {
        int d = __ldg(dst + i);
        int p = atomicAdd(cur + d, 1);
        eidx[__ldg(row + d) + p] = __ldg(src + i);
    }
}

// ---------------------------------------------------------------------------
// gather-sum: one warp per dst row. Lane-parallel eidx load + shfl broadcast,
// 4-edge unrolled groups -> 8 independent LDG.128 in flight. Plain stores.
// ---------------------------------------------------------------------------
__global__ void __launch_bounds__(256) gather_sum_kernel(
    const float* __restrict__ tab,
    const int*   __restrict__ eidx,
    const int*   __restrict__ row,
    float*       __restrict__ agg,
    int nrows)
{
    int r = (blockIdx.x * blockDim.x + threadIdx.x) >> 5;
    int lane = threadIdx.x & 31;
    if (r >= nrows) return;
    int e0 = __ldg(row + r);
    int e1 = __ldg(row + r + 1);
    float4 acc0 = make_float4(0.f, 0.f, 0.f, 0.f);
    float4 acc1 = make_float4(0.f, 0.f, 0.f, 0.f);

    for (int base = e0; base < e1; base += 32) {
        int rem = e1 - base;
        int cnt = rem < 32 ? rem : 32;
        int idx = (lane < cnt) ? __ldg(eidx + base + lane) : 0;
        int j = 0;
        for (; j + 4 <= cnt; j += 4) {
            int s0 = __shfl_sync(0xffffffffu, idx, j);
            int s1 = __shfl_sync(0xffffffffu, idx, j + 1);
            int s2 = __shfl_sync(0xffffffffu, idx, j + 2);
            int s3 = __shfl_sync(0xffffffffu, idx, j + 3);
            const float4* p0 = (const float4*)(tab + (size_t)s0 * DIM);
            const float4* p1 = (const float4*)(tab + (size_t)s1 * DIM);
            const float4* p2 = (const float4*)(tab + (size_t)s2 * DIM);
            const float4* p3 = (const float4*)(tab + (size_t)s3 * DIM);
            float4 a0 = __ldg(p0 + lane), b0 = __ldg(p0 + lane + 32);
            float4 a1 = __ldg(p1 + lane), b1 = __ldg(p1 + lane + 32);
            float4 a2 = __ldg(p2 + lane), b2 = __ldg(p2 + lane + 32);
            float4 a3 = __ldg(p3 + lane), b3 = __ldg(p3 + lane + 32);
            acc0.x += a0.x + a1.x + a2.x + a3.x;
            acc0.y += a0.y + a1.y + a2.y + a3.y;
            acc0.z += a0.z + a1.z + a2.z + a3.z;
            acc0.w += a0.w + a1.w + a2.w + a3.w;
            acc1.x += b0.x + b1.x + b2.x + b3.x;
            acc1.y += b0.y + b1.y + b2.y + b3.y;
            acc1.z += b0.z + b1.z + b2.z + b3.z;
            acc1.w += b0.w + b1.w + b2.w + b3.w;
        }
        for (; j < cnt; j++) {
            int s = __shfl_sync(0xffffffffu, idx, j);
            const float4* p = (const float4*)(tab + (size_t)s * DIM);
            float4 a = __ldg(p + lane), b = __ldg(p + lane + 32);
            acc0.x += a.x; acc0.y += a.y; acc0.z += a.z; acc0.w += a.w;
            acc1.x += b.x; acc1.y += b.y; acc1.z += b.z; acc1.w += b.w;
        }
    }
    float4* o = (float4*)(agg + (size_t)r * DIM);
    o[lane]      = acc0;
    o[lane + 32] = acc1;
}

// ---------------------------------------------------------------------------
// cp.async double-buffered tiled fp32 GEMM (unchanged from R5)
// ---------------------------------------------------------------------------
template<int BM, int BN, int BK, int TM, int TN, bool ACC, bool RELU, bool HASBIAS>
__global__ void __launch_bounds__((BM / TM) * (BN / TN), 2) sgemm_kernel(
    int M, int K,
    const float* __restrict__ A, int lda, int zA,
    const float* __restrict__ B, int ldb, int zB,
    const float* __restrict__ bias,
    const float* __restrict__ Cin,
    float*       __restrict__ Cout, int ldc, int zC)
{
    constexpr int TX = BN / TN;
    constexpr int TY = BM / TM;
    constexpr int NT = TX * TY;
    constexpr int AV = (BM * BK / 4) / NT;
    constexpr int BV = (BN * BK / 4) / NT;
    static_assert(AV >= 1 && BV >= 1, "tile too small");

    __shared__ float As[2][BM][BK + 4];
    __shared__ float Bs[2][BK][BN + 4];

    const int tid = threadIdx.x;
    const int tx = tid % TX;
    const int ty = tid / TX;
    const int rowBase = blockIdx.y * BM;
    const int colBase = blockIdx.x * BN;
    const int colOff  = blockIdx.z * zC;

    A += (size_t)blockIdx.z * zA;
    B += (size_t)blockIdx.z * zB;

    auto loadTile = [&](int k0, int buf) {
#pragma unroll
        for (int l = 0; l < AV; l++) {
            int idx = tid + l * NT;
            int r = idx / (BK / 4);
            int c = idx % (BK / 4);
            int grow = rowBase + r;
            int ok = (grow < M) ? 16 : 0;
            int gclamp = (grow < M) ? grow : (M - 1);
            uint32_t sa = (uint32_t)__cvta_generic_to_shared(&As[buf][r][c * 4]);
            cp_async16(sa, A + (size_t)gclamp * lda + k0 + c * 4, ok);
        }
#pragma unroll
        for (int l = 0; l < BV; l++) {
            int idx = tid + l * NT;
            int kr = idx / (BN / 4);
            int c  = idx % (BN / 4);
            uint32_t sb = (uint32_t)__cvta_generic_to_shared(&Bs[buf][kr][c * 4]);
            cp_async16(sb, B + (size_t)(k0 + kr) * ldb + colBase + c * 4, 16);
        }
    };

    float acc[TM][TN];
#pragma unroll
    for (int i = 0; i < TM; i++)
#pragma unroll
        for (int j = 0; j < TN; j++) acc[i][j] = 0.f;

    const int KT = K / BK;
    loadTile(0, 0);
    cp_commit();

    for (int kt = 0; kt < KT; kt++) {
        const int cur = kt & 1;
        const int nxt = cur ^ 1;
        if (kt + 1 < KT) {
            loadTile((kt + 1) * BK, nxt);
            cp_commit();
            cp_wait<1>();
        } else {
            cp_wait<0>();
        }
        __syncthreads();

#pragma unroll
        for (int kg = 0; kg < BK; kg += 4) {
            float4 a4[TM];
#pragma unroll
            for (int i = 0; i < TM; i++)
                a4[i] = *(const float4*)&As[cur][ty * TM + i][kg];
#pragma unroll
            for (int kk = 0; kk < 4; kk++) {
                float bf[TN];
#pragma unroll
                for (int j = 0; j < TN; j += 4) {
                    float4 t = *(const float4*)&Bs[cur][kg + kk][tx * TN + j];
                    bf[j] = t.x; bf[j + 1] = t.y; bf[j + 2] = t.z; bf[j + 3] = t.w;
                }
#pragma unroll
                for (int i = 0; i < TM; i++) {
                    float a = (kk == 0) ? a4[i].x : (kk == 1) ? a4[i].y
                             : (kk == 2) ? a4[i].z : a4[i].w;
#pragma unroll
                    for (int j = 0; j < TN; j++)
                        acc[i][j] = fmaf(a, bf[j], acc[i][j]);
                }
            }
        }
        __syncthreads();
    }

#pragma unroll
    for (int i = 0; i < TM; i++) {
        int row = rowBase + ty * TM + i;
        if (row < M) {
#pragma unroll
            for (int j = 0; j < TN; j += 4) {
                int col = colOff + colBase + tx * TN + j;
                float4 v = make_float4(acc[i][j], acc[i][j + 1], acc[i][j + 2], acc[i][j + 3]);
                if constexpr (HASBIAS) {
                    float4 bv = *(const float4*)(bias + col);
                    v.x += bv.x; v.y += bv.y; v.z += bv.z; v.w += bv.w;
                }
                if constexpr (ACC) {
                    float4 cv = *(const float4*)(Cin + (size_t)row * ldc + col);
                    v.x += cv.x; v.y += cv.y; v.z += cv.z; v.w += cv.w;
                }
                if constexpr (RELU) {
                    v.x = fmaxf(v.x, 0.f); v.y = fmaxf(v.y, 0.f);
                    v.z = fmaxf(v.z, 0.f); v.w = fmaxf(v.w, 0.f);
                }
                *(float4*)(Cout + (size_t)row * ldc + col) = v;
            }
        }
    }
}

// ---------------------------------------------------------------------------
// Link prediction head
// ---------------------------------------------------------------------------
__global__ void __launch_bounds__(128) pred_kernel(
    const float* __restrict__ h,
    const int*   __restrict__ ps, const int* __restrict__ pd,
    const int*   __restrict__ ns, const int* __restrict__ nd,
    const float* __restrict__ pw1, const float* __restrict__ pb1,
    const float* __restrict__ pw2, const float* __restrict__ pb2,
    float*       __restrict__ out, int npair)
{
    constexpr int P = 16;
    __shared__ float e[P][DIM];
    __shared__ float sred[P][4];

    int tid = threadIdx.x;
    int base = blockIdx.x * P;

#pragma unroll
    for (int p = 0; p < P; p++) {
        if (tid < 64) {
            int g = base + p;
            int s, d;
            if (g < npair) { s = __ldg(ps + g);         d = __ldg(pd + g); }
            else           { s = __ldg(ns + g - npair); d = __ldg(nd + g - npair); }
            const float4* hs = (const float4*)(h + (size_t)s * DIM);
            const float4* hd = (const float4*)(h + (size_t)d * DIM);
            float4 a = __ldg(hs + tid);
            float4 b = __ldg(hd + tid);
            *(float4*)&e[p][tid * 4] = make_float4(a.x * b.x, a.y * b.y, a.z * b.z, a.w * b.w);
        }
    }
    __syncthreads();

    float accp[P];
#pragma unroll
    for (int p = 0; p < P; p++) accp[p] = 0.f;

    for (int i = 0; i < DIM; i++) {
        float w = __ldg(pw1 + i * 128 + tid);
#pragma unroll
        for (int p = 0; p < P; p++) accp[p] = fmaf(e[p][i], w, accp[p]);
    }

    float w2  = __ldg(pw2 + tid);
    float b1v = __ldg(pb1 + tid);
    int lane = tid & 31;
    int wid  = tid >> 5;
#pragma unroll
    for (int p = 0; p < P; p++) {
        float z = fmaxf(accp[p] + b1v, 0.f) * w2;
#pragma unroll
        for (int o = 16; o > 0; o >>= 1) z += __shfl_down_sync(0xffffffffu, z, o);
        if (lane == 0) sred[p][wid] = z;
    }
    __syncthreads();
    if (tid < P) {
        out[base + tid] = sred[tid][0] + sred[tid][1] + sred[tid][2] + sred[tid][3] + pb2[0];
    }
}

// ---------------------------------------------------------------------------
// launch
// ---------------------------------------------------------------------------
extern "C" void kernel_launch(void* const* d_in, const int* in_sizes, int n_in,
                              void* d_out, int out_size)
{
    const float* x     = (const float*)d_in[0];
    const int* src0    = (const int*)d_in[1];
    const int* dst0    = (const int*)d_in[2];
    const int* src1    = (const int*)d_in[3];
    const int* dst1    = (const int*)d_in[4];
    const int* pos_src = (const int*)d_in[5];
    const int* pos_dst = (const int*)d_in[6];
    const int* neg_src = (const int*)d_in[7];
    const int* neg_dst = (const int*)d_in[8];
    const float* W0    = (const float*)d_in[9];
    const float* loop0 = (const float*)d_in[10];
    const float* b0    = (const float*)d_in[11];
    const float* W1    = (const float*)d_in[12];
    const float* loop1 = (const float*)d_in[13];
    const float* b1    = (const float*)d_in[14];
    const float* pw1   = (const float*)d_in[15];
    const float* pb1   = (const float*)d_in[16];
    const float* pw2   = (const float*)d_in[17];
    const float* pb2   = (const float*)d_in[18];

    const int E0 = in_sizes[1];
    const int E1 = in_sizes[3];
    const int NP = in_sizes[5];

    float *agg0, *h0, *agg1, *h1;
    cudaGetSymbolAddress((void**)&agg0, g_agg0);
    cudaGetSymbolAddress((void**)&h0,   g_h0);
    cudaGetSymbolAddress((void**)&agg1, g_agg1);
    cudaGetSymbolAddress((void**)&h1,   g_h1);
    int *deg0, *cur0, *row0, *eidx0, *deg1, *cur1, *row1, *eidx1, *bsum, *boff;
    cudaGetSymbolAddress((void**)&deg0,  g_deg0);
    cudaGetSymbolAddress((void**)&cur0,  g_cur0);
    cudaGetSymbolAddress((void**)&row0,  g_row0);
    cudaGetSymbolAddress((void**)&eidx0, g_eidx0);
    cudaGetSymbolAddress((void**)&deg1,  g_deg1);
    cudaGetSymbolAddress((void**)&cur1,  g_cur1);
    cudaGetSymbolAddress((void**)&row1,  g_row1);
    cudaGetSymbolAddress((void**)&eidx1, g_eidx1);
    cudaGetSymbolAddress((void**)&bsum,  g_bsum);
    cudaGetSymbolAddress((void**)&boff,  g_boff);

    float* out   = (float*)d_out;
    float* out_h = out + 2 * NP;   // [10000, 256] final embeddings

    const int NB0 = (NDST0 + 1023) / 1024;   // 49
    const int NB1 = (NDST1 + 1023) / 1024;   // 10

    // ---------------- layer 0 ----------------
    zero16_kernel<<<(NDST0 / 4 + 255) / 256, 256>>>(deg0, NDST0 / 4);
    zero16_kernel<<<(NDST0 / 4 + 255) / 256, 256>>>(cur0, NDST0 / 4);
    hist_kernel<<<(E0 + 255) / 256, 256>>>(dst0, deg0, E0);
    block_scan_kernel<<<NB0, 1024>>>(deg0, row0, bsum, NDST0);
    bsum_scan_kernel<<<1, 32>>>(bsum, boff, NB0);
    add_off_kernel<<<(NDST0 + 255) / 256, 256>>>(row0, boff, NDST0, NB0);
    place_kernel<<<(E0 + 255) / 256, 256>>>(src0, dst0, row0, cur0, eidx0, E0);
    gather_sum_kernel<<<(NDST0 * 32 + 255) / 256, 256>>>(x, eidx0, row0, agg0, NDST0);

    // h0_pre = x[:50000] @ loop0 + b0
    {
        dim3 grid(DIM / 128, (NDST0 + 127) / 128, 1);
        sgemm_kernel<128, 128, 16, 8, 8, false, false, true><<<grid, 256>>>(
            NDST0, DIM, x, DIM, 0, loop0, DIM, 0, b0, nullptr, h0, DIM, 0);
    }
    // h0 = relu( bdd(agg0, W0) + h0_pre )
    {
        dim3 grid(1, (NDST0 + 127) / 128, 4);
        sgemm_kernel<128, 64, 16, 8, 4, true, true, false><<<grid, 256>>>(
            NDST0, 64, agg0, DIM, 64, W0, 64, 64 * 64, nullptr, h0, h0, DIM, 64);
    }

    // ---------------- layer 1 ----------------
    zero16_kernel<<<(NDST1 / 4 + 255) / 256, 256>>>(deg1, NDST1 / 4);
    zero16_kernel<<<(NDST1 / 4 + 255) / 256, 256>>>(cur1, NDST1 / 4);
    hist_kernel<<<(E1 + 255) / 256, 256>>>(dst1, deg1, E1);
    block_scan_kernel<<<NB1, 1024>>>(deg1, row1, bsum, NDST1);
    bsum_scan_kernel<<<1, 32>>>(bsum, boff, NB1);
    add_off_kernel<<<(NDST1 + 255) / 256, 256>>>(row1, boff, NDST1, NB1);
    place_kernel<<<(E1 + 255) / 256, 256>>>(src1, dst1, row1, cur1, eidx1, E1);
    gather_sum_kernel<<<(NDST1 * 32 + 255) / 256, 256>>>(h0, eidx1, row1, agg1, NDST1);

    {
        dim3 grid(DIM / 128, (NDST1 + 127) / 128, 1);
        sgemm_kernel<128, 128, 16, 8, 8, false, false, true><<<grid, 256>>>(
            NDST1, DIM, h0, DIM, 0, loop1, DIM, 0, b1, nullptr, h1, DIM, 0);
    }
    {
        dim3 grid(1, (NDST1 + 127) / 128, 4);
        sgemm_kernel<128, 64, 16, 8, 4, true, true, false><<<grid, 256>>>(
            NDST1, 64, agg1, DIM, 64, W1, 64, 64 * 64, nullptr, h1, out_h, DIM, 64);
    }

    // prediction head: 10000 pairs -> out[0:10000]
    pred_kernel<<<(2 * NP) / 16, 128>>>(out_h, pos_src, pos_dst, neg_src, neg_dst,
                                        pw1, pb1, pw2, pb2, out, NP);
}

// round 10
// speedup vs baseline: 1.2421x; 1.0827x over previous
#include <cuda_runtime.h>
#include <cstdint>

// Problem constants (fixed by dataset)
constexpr int NSRC0 = 200000;
constexpr int NDST0 = 50000;
constexpr int NDST1 = 10000;
constexpr int DIM   = 256;
constexpr int E0MAX = 800000;
constexpr int E1MAX = 160000;
constexpr int NB0   = (NDST0 + 1023) / 1024;   // 49
constexpr int NB1   = (NDST1 + 1023) / 1024;   // 10

// Static scratch (no allocation allowed)
__device__ float g_agg0[(size_t)NDST0 * DIM];
__device__ float g_h0  [(size_t)NDST0 * DIM];
__device__ float g_agg1[(size_t)NDST1 * DIM];
__device__ float g_h1  [(size_t)NDST1 * DIM];

// CSR scratch
__device__ int g_deg0[NDST0];
__device__ int g_row0[NDST0];
__device__ int g_eidx0[E0MAX];
__device__ int g_deg1[NDST1];
__device__ int g_row1[NDST1];
__device__ int g_eidx1[E1MAX];
__device__ int g_bsum0[NB0];
__device__ int g_boff0[NB0];
__device__ int g_bsum1[NB1];
__device__ int g_boff1[NB1];

// ---------------------------------------------------------------------------
// cp.async helpers
// ---------------------------------------------------------------------------
__device__ __forceinline__ void cp_async16(uint32_t smem_addr, const void* gptr, int src_bytes) {
    asm volatile("cp.async.ca.shared.global [%0], [%1], 16, %2;\n"
                 :: "r"(smem_addr), "l"(gptr), "r"(src_bytes));
}
__device__ __forceinline__ void cp_commit() {
    asm volatile("cp.async.commit_group;\n" ::: "memory");
}
template<int N>
__device__ __forceinline__ void cp_wait() {
    asm volatile("cp.async.wait_group %0;\n" :: "n"(N) : "memory");
}

// ---------------------------------------------------------------------------
// CSR build, both layers fused per step
// ---------------------------------------------------------------------------
__global__ void zero_deg_kernel(int* __restrict__ deg0, int* __restrict__ deg1) {
    int i = blockIdx.x * blockDim.x + threadIdx.x;           // 16B granules
    if (i < NDST0 / 4)                 ((int4*)deg0)[i] = make_int4(0, 0, 0, 0);
    else if (i < NDST0 / 4 + NDST1 / 4) ((int4*)deg1)[i - NDST0 / 4] = make_int4(0, 0, 0, 0);
}

__global__ void hist_kernel(const int* __restrict__ dst0, int* __restrict__ deg0, int E0,
                            const int* __restrict__ dst1, int* __restrict__ deg1, int E1) {
    int i = blockIdx.x * blockDim.x + threadIdx.x;
    if (i < E0)           atomicAdd(deg0 + __ldg(dst0 + i), 1);
    else if (i < E0 + E1) atomicAdd(deg1 + __ldg(dst1 + i - E0), 1);
}

// per-block exclusive scan (1024 elems/block, coalesced, shfl-based)
__device__ __forceinline__ void block_scan_body(
    const int* __restrict__ deg, int* __restrict__ row,
    int* __restrict__ bsum, int n, int b)
{
    __shared__ int wsum[32];
    int tid = threadIdx.x;
    int i = b * 1024 + tid;
    int v = (i < n) ? deg[i] : 0;
    int lane = tid & 31, wid = tid >> 5;
    int s = v;
#pragma unroll
    for (int o = 1; o < 32; o <<= 1) {
        int t = __shfl_up_sync(0xffffffffu, s, o);
        if (lane >= o) s += t;
    }
    if (lane == 31) wsum[wid] = s;
    __syncthreads();
    if (wid == 0) {
        int ws = wsum[lane];
#pragma unroll
        for (int o = 1; o < 32; o <<= 1) {
            int t = __shfl_up_sync(0xffffffffu, ws, o);
            if (lane >= o) ws += t;
        }
        wsum[lane] = ws;
    }
    __syncthreads();
    int excl = s - v + (wid > 0 ? wsum[wid - 1] : 0);
    if (i < n) row[i] = excl;
    if (tid == 0) bsum[b] = wsum[31];
}

__global__ void __launch_bounds__(1024) block_scan_kernel(
    const int* __restrict__ deg0, int* __restrict__ row0, int* __restrict__ bsum0,
    const int* __restrict__ deg1, int* __restrict__ row1, int* __restrict__ bsum1)
{
    if (blockIdx.x < NB0) block_scan_body(deg0, row0, bsum0, NDST0, blockIdx.x);
    else                  block_scan_body(deg1, row1, bsum1, NDST1, blockIdx.x - NB0);
}

__global__ void bsum_scan_kernel(const int* __restrict__ bsum0, int* __restrict__ boff0,
                                 const int* __restrict__ bsum1, int* __restrict__ boff1) {
    if (threadIdx.x == 0) {
        if (blockIdx.x == 0) {
            int run = 0;
            for (int b = 0; b < NB0; b++) { boff0[b] = run; run += bsum0[b]; }
        } else {
            int run = 0;
            for (int b = 0; b < NB1; b++) { boff1[b] = run; run += bsum1[b]; }
        }
    }
}

__global__ void add_off_kernel(int* __restrict__ row0, const int* __restrict__ boff0,
                               int* __restrict__ row1, const int* __restrict__ boff1) {
    int i = blockIdx.x * blockDim.x + threadIdx.x;
    if (i < NDST0) row0[i] += __ldg(boff0 + (i >> 10));
    else if (i < NDST0 + NDST1) {
        int j = i - NDST0;
        row1[j] += __ldg(boff1 + (j >> 10));
    }
}

// place mutates row: afterwards row[d] = end offset of segment d.
__global__ void place_kernel(const int* __restrict__ src0, const int* __restrict__ dst0,
                             int* __restrict__ row0, int* __restrict__ eidx0, int E0,
                             const int* __restrict__ src1, const int* __restrict__ dst1,
                             int* __restrict__ row1, int* __restrict__ eidx1, int E1) {
    int i = blockIdx.x * blockDim.x + threadIdx.x;
    if (i < E0) {
        int d = __ldg(dst0 + i);
        int p = atomicAdd(row0 + d, 1);
        eidx0[p] = __ldg(src0 + i);
    } else if (i < E0 + E1) {
        int j = i - E0;
        int d = __ldg(dst1 + j);
        int p = atomicAdd(row1 + d, 1);
        eidx1[p] = __ldg(src1 + j);
    }
}

// ---------------------------------------------------------------------------
// gather body: one warp per dst row; row[] holds END offsets (post-place).
// e0 = row[r-1] (or 0), e1 = row[r]. Lane-parallel eidx + shfl broadcast,
// 4-edge unrolled groups -> 8 independent LDG.128 in flight. Plain stores.
// ---------------------------------------------------------------------------
__device__ void gather_body(
    const float* __restrict__ tab,
    const int*   __restrict__ eidx,
    const int*   __restrict__ row,
    float*       __restrict__ agg,
    int nrows, int gb)
{
    int r = gb * 8 + (threadIdx.x >> 5);
    int lane = threadIdx.x & 31;
    if (r >= nrows) return;
    int e0 = (r > 0) ? __ldg(row + r - 1) : 0;
    int e1 = __ldg(row + r);
    float4 acc0 = make_float4(0.f, 0.f, 0.f, 0.f);
    float4 acc1 = make_float4(0.f, 0.f, 0.f, 0.f);

    for (int base = e0; base < e1; base += 32) {
        int rem = e1 - base;
        int cnt = rem < 32 ? rem : 32;
        int idx = (lane < cnt) ? __ldg(eidx + base + lane) : 0;
        int j = 0;
        for (; j + 4 <= cnt; j += 4) {
            int s0 = __shfl_sync(0xffffffffu, idx, j);
            int s1 = __shfl_sync(0xffffffffu, idx, j + 1);
            int s2 = __shfl_sync(0xffffffffu, idx, j + 2);
            int s3 = __shfl_sync(0xffffffffu, idx, j + 3);
            const float4* p0 = (const float4*)(tab + (size_t)s0 * DIM);
            const float4* p1 = (const float4*)(tab + (size_t)s1 * DIM);
            const float4* p2 = (const float4*)(tab + (size_t)s2 * DIM);
            const float4* p3 = (const float4*)(tab + (size_t)s3 * DIM);
            float4 a0 = __ldg(p0 + lane), b0 = __ldg(p0 + lane + 32);
            float4 a1 = __ldg(p1 + lane), b1 = __ldg(p1 + lane + 32);
            float4 a2 = __ldg(p2 + lane), b2 = __ldg(p2 + lane + 32);
            float4 a3 = __ldg(p3 + lane), b3 = __ldg(p3 + lane + 32);
            acc0.x += a0.x + a1.x + a2.x + a3.x;
            acc0.y += a0.y + a1.y + a2.y + a3.y;
            acc0.z += a0.z + a1.z + a2.z + a3.z;
            acc0.w += a0.w + a1.w + a2.w + a3.w;
            acc1.x += b0.x + b1.x + b2.x + b3.x;
            acc1.y += b0.y + b1.y + b2.y + b3.y;
            acc1.z += b0.z + b1.z + b2.z + b3.z;
            acc1.w += b0.w + b1.w + b2.w + b3.w;
        }
        for (; j < cnt; j++) {
            int s = __shfl_sync(0xffffffffu, idx, j);
            const float4* p = (const float4*)(tab + (size_t)s * DIM);
            float4 a = __ldg(p + lane), b = __ldg(p + lane + 32);
            acc0.x += a.x; acc0.y += a.y; acc0.z += a.z; acc0.w += a.w;
            acc1.x += b.x; acc1.y += b.y; acc1.z += b.z; acc1.w += b.w;
        }
    }
    float4* o = (float4*)(agg + (size_t)r * DIM);
    o[lane]      = acc0;
    o[lane + 32] = acc1;
}

// ---------------------------------------------------------------------------
// cp.async double-buffered GEMM body (bias, no acc/relu) used by fused kernel
// ---------------------------------------------------------------------------
template<int BM, int BN, int BK, int TM, int TN>
__device__ void sgemm_body(
    int M, int K,
    const float* __restrict__ A, int lda,
    const float* __restrict__ B, int ldb,
    const float* __restrict__ bias,
    float* __restrict__ Cout, int ldc,
    int bx, int by)
{
    constexpr int TX = BN / TN;
    constexpr int TY = BM / TM;
    constexpr int NT = TX * TY;
    constexpr int AV = (BM * BK / 4) / NT;
    constexpr int BV = (BN * BK / 4) / NT;

    __shared__ float As[2][BM][BK + 4];
    __shared__ float Bs[2][BK][BN + 4];

    const int tid = threadIdx.x;
    const int tx = tid % TX;
    const int ty = tid / TX;
    const int rowBase = by * BM;
    const int colBase = bx * BN;

    auto loadTile = [&](int k0, int buf) {
#pragma unroll
        for (int l = 0; l < AV; l++) {
            int idx = tid + l * NT;
            int r = idx / (BK / 4);
            int c = idx % (BK / 4);
            int grow = rowBase + r;
            int ok = (grow < M) ? 16 : 0;
            int gclamp = (grow < M) ? grow : (M - 1);
            uint32_t sa = (uint32_t)__cvta_generic_to_shared(&As[buf][r][c * 4]);
            cp_async16(sa, A + (size_t)gclamp * lda + k0 + c * 4, ok);
        }
#pragma unroll
        for (int l = 0; l < BV; l++) {
            int idx = tid + l * NT;
            int kr = idx / (BN / 4);
            int c  = idx % (BN / 4);
            uint32_t sb = (uint32_t)__cvta_generic_to_shared(&Bs[buf][kr][c * 4]);
            cp_async16(sb, B + (size_t)(k0 + kr) * ldb + colBase + c * 4, 16);
        }
    };

    float acc[TM][TN];
#pragma unroll
    for (int i = 0; i < TM; i++)
#pragma unroll
        for (int j = 0; j < TN; j++) acc[i][j] = 0.f;

    const int KT = K / BK;
    loadTile(0, 0);
    cp_commit();

    for (int kt = 0; kt < KT; kt++) {
        const int cur = kt & 1;
        const int nxt = cur ^ 1;
        if (kt + 1 < KT) {
            loadTile((kt + 1) * BK, nxt);
            cp_commit();
            cp_wait<1>();
        } else {
            cp_wait<0>();
        }
        __syncthreads();

#pragma unroll
        for (int kg = 0; kg < BK; kg += 4) {
            float4 a4[TM];
#pragma unroll
            for (int i = 0; i < TM; i++)
                a4[i] = *(const float4*)&As[cur][ty * TM + i][kg];
#pragma unroll
            for (int kk = 0; kk < 4; kk++) {
                float bf[TN];
#pragma unroll
                for (int j = 0; j < TN; j += 4) {
                    float4 t = *(const float4*)&Bs[cur][kg + kk][tx * TN + j];
                    bf[j] = t.x; bf[j + 1] = t.y; bf[j + 2] = t.z; bf[j + 3] = t.w;
                }
#pragma unroll
                for (int i = 0; i < TM; i++) {
                    float a = (kk == 0) ? a4[i].x : (kk == 1) ? a4[i].y
                             : (kk == 2) ? a4[i].z : a4[i].w;
#pragma unroll
                    for (int j = 0; j < TN; j++)
                        acc[i][j] = fmaf(a, bf[j], acc[i][j]);
                }
            }
        }
        __syncthreads();
    }

#pragma unroll
    for (int i = 0; i < TM; i++) {
        int row = rowBase + ty * TM + i;
        if (row < M) {
#pragma unroll
            for (int j = 0; j < TN; j += 4) {
                int col = colBase + tx * TN + j;
                float4 v = make_float4(acc[i][j], acc[i][j + 1], acc[i][j + 2], acc[i][j + 3]);
                float4 bv = *(const float4*)(bias + col);
                v.x += bv.x; v.y += bv.y; v.z += bv.z; v.w += bv.w;
                *(float4*)(Cout + (size_t)row * ldc + col) = v;
            }
        }
    }
}

// ---------------------------------------------------------------------------
// fused kernel: blocks [0,gemmBlocks) run self-loop GEMM; rest run gather.
// Independent outputs (h vs agg) -> safe concurrency, overlaps FMA with DRAM.
// ---------------------------------------------------------------------------
template<int BM, int BN, int BK, int TM, int TN>
__global__ void __launch_bounds__(256, 2) fused_loop_gather_kernel(
    int M, int K,
    const float* __restrict__ A, int lda,
    const float* __restrict__ B, int ldb,
    const float* __restrict__ bias,
    float* __restrict__ Cout, int ldc,
    int gemmBlocks, int gemmGridX,
    const float* __restrict__ tab,
    const int*   __restrict__ eidx,
    const int*   __restrict__ row,
    float*       __restrict__ agg,
    int nrows)
{
    if ((int)blockIdx.x < gemmBlocks) {
        sgemm_body<BM, BN, BK, TM, TN>(M, K, A, lda, B, ldb, bias, Cout, ldc,
                                       blockIdx.x % gemmGridX, blockIdx.x / gemmGridX);
    } else {
        gather_body(tab, eidx, row, agg, nrows, blockIdx.x - gemmBlocks);
    }
}

// ---------------------------------------------------------------------------
// bdd GEMM (block-diagonal, ACC + RELU), cp.async, z = base index
// ---------------------------------------------------------------------------
template<int BM, int BN, int BK, int TM, int TN>
__global__ void __launch_bounds__((BM / TM) * (BN / TN), 2) bdd_gemm_kernel(
    int M, int K,
    const float* __restrict__ A, int lda, int zA,
    const float* __restrict__ B, int ldb, int zB,
    const float* __restrict__ Cin,
    float*       __restrict__ Cout, int ldc, int zC)
{
    constexpr int TX = BN / TN;
    constexpr int TY = BM / TM;
    constexpr int NT = TX * TY;
    constexpr int AV = (BM * BK / 4) / NT;
    constexpr int BV = (BN * BK / 4) / NT;

    __shared__ float As[2][BM][BK + 4];
    __shared__ float Bs[2][BK][BN + 4];

    const int tid = threadIdx.x;
    const int tx = tid % TX;
    const int ty = tid / TX;
    const int rowBase = blockIdx.y * BM;
    const int colBase = blockIdx.x * BN;
    const int colOff  = blockIdx.z * zC;

    A += (size_t)blockIdx.z * zA;
    B += (size_t)blockIdx.z * zB;

    auto loadTile = [&](int k0, int buf) {
#pragma unroll
        for (int l = 0; l < AV; l++) {
            int idx = tid + l * NT;
            int r = idx / (BK / 4);
            int c = idx % (BK / 4);
            int grow = rowBase + r;
            int ok = (grow < M) ? 16 : 0;
            int gclamp = (grow < M) ? grow : (M - 1);
            uint32_t sa = (uint32_t)__cvta_generic_to_shared(&As[buf][r][c * 4]);
            cp_async16(sa, A + (size_t)gclamp * lda + k0 + c * 4, ok);
        }
#pragma unroll
        for (int l = 0; l < BV; l++) {
            int idx = tid + l * NT;
            int kr = idx / (BN / 4);
            int c  = idx % (BN / 4);
            uint32_t sb = (uint32_t)__cvta_generic_to_shared(&Bs[buf][kr][c * 4]);
            cp_async16(sb, B + (size_t)(k0 + kr) * ldb + colBase + c * 4, 16);
        }
    };

    float acc[TM][TN];
#pragma unroll
    for (int i = 0; i < TM; i++)
#pragma unroll
        for (int j = 0; j < TN; j++) acc[i][j] = 0.f;

    const int KT = K / BK;
    loadTile(0, 0);
    cp_commit();

    for (int kt = 0; kt < KT; kt++) {
        const int cur = kt & 1;
        const int nxt = cur ^ 1;
        if (kt + 1 < KT) {
            loadTile((kt + 1) * BK, nxt);
            cp_commit();
            cp_wait<1>();
        } else {
            cp_wait<0>();
        }
        __syncthreads();

#pragma unroll
        for (int kg = 0; kg < BK; kg += 4) {
            float4 a4[TM];
#pragma unroll
            for (int i = 0; i < TM; i++)
                a4[i] = *(const float4*)&As[cur][ty * TM + i][kg];
#pragma unroll
            for (int kk = 0; kk < 4; kk++) {
                float bf[TN];
#pragma unroll
                for (int j = 0; j < TN; j += 4) {
                    float4 t = *(const float4*)&Bs[cur][kg + kk][tx * TN + j];
                    bf[j] = t.x; bf[j + 1] = t.y; bf[j + 2] = t.z; bf[j + 3] = t.w;
                }
#pragma unroll
                for (int i = 0; i < TM; i++) {
                    float a = (kk == 0) ? a4[i].x : (kk == 1) ? a4[i].y
                             : (kk == 2) ? a4[i].z : a4[i].w;
#pragma unroll
                    for (int j = 0; j < TN; j++)
                        acc[i][j] = fmaf(a, bf[j], acc[i][j]);
                }
            }
        }
        __syncthreads();
    }

#pragma unroll
    for (int i = 0; i < TM; i++) {
        int row = rowBase + ty * TM + i;
        if (row < M) {
#pragma unroll
            for (int j = 0; j < TN; j += 4) {
                int col = colOff + colBase + tx * TN + j;
                float4 v = make_float4(acc[i][j], acc[i][j + 1], acc[i][j + 2], acc[i][j + 3]);
                float4 cv = *(const float4*)(Cin + (size_t)row * ldc + col);
                v.x = fmaxf(v.x + cv.x, 0.f);
                v.y = fmaxf(v.y + cv.y, 0.f);
                v.z = fmaxf(v.z + cv.z, 0.f);
                v.w = fmaxf(v.w + cv.w, 0.f);
                *(float4*)(Cout + (size_t)row * ldc + col) = v;
            }
        }
    }
}

// ---------------------------------------------------------------------------
// Link prediction head
// ---------------------------------------------------------------------------
__global__ void __launch_bounds__(128) pred_kernel(
    const float* __restrict__ h,
    const int*   __restrict__ ps, const int* __restrict__ pd,
    const int*   __restrict__ ns, const int* __restrict__ nd,
    const float* __restrict__ pw1, const float* __restrict__ pb1,
    const float* __restrict__ pw2, const float* __restrict__ pb2,
    float*       __restrict__ out, int npair)
{
    constexpr int P = 16;
    __shared__ float e[P][DIM];
    __shared__ float sred[P][4];

    int tid = threadIdx.x;
    int base = blockIdx.x * P;

#pragma unroll
    for (int p = 0; p < P; p++) {
        if (tid < 64) {
            int g = base + p;
            int s, d;
            if (g < npair) { s = __ldg(ps + g);         d = __ldg(pd + g); }
            else           { s = __ldg(ns + g - npair); d = __ldg(nd + g - npair); }
            const float4* hs = (const float4*)(h + (size_t)s * DIM);
            const float4* hd = (const float4*)(h + (size_t)d * DIM);
            float4 a = __ldg(hs + tid);
            float4 b = __ldg(hd + tid);
            *(float4*)&e[p][tid * 4] = make_float4(a.x * b.x, a.y * b.y, a.z * b.z, a.w * b.w);
        }
    }
    __syncthreads();

    float accp[P];
#pragma unroll
    for (int p = 0; p < P; p++) accp[p] = 0.f;

    for (int i = 0; i < DIM; i++) {
        float w = __ldg(pw1 + i * 128 + tid);
#pragma unroll
        for (int p = 0; p < P; p++) accp[p] = fmaf(e[p][i], w, accp[p]);
    }

    float w2  = __ldg(pw2 + tid);
    float b1v = __ldg(pb1 + tid);
    int lane = tid & 31;
    int wid  = tid >> 5;
#pragma unroll
    for (int p = 0; p < P; p++) {
        float z = fmaxf(accp[p] + b1v, 0.f) * w2;
#pragma unroll
        for (int o = 16; o > 0; o >>= 1) z += __shfl_down_sync(0xffffffffu, z, o);
        if (lane == 0) sred[p][wid] = z;
    }
    __syncthreads();
    if (tid < P) {
        out[base + tid] = sred[tid][0] + sred[tid][1] + sred[tid][2] + sred[tid][3] + pb2[0];
    }
}

// ---------------------------------------------------------------------------
// launch
// ---------------------------------------------------------------------------
extern "C" void kernel_launch(void* const* d_in, const int* in_sizes, int n_in,
                              void* d_out, int out_size)
{
    const float* x     = (const float*)d_in[0];
    const int* src0    = (const int*)d_in[1];
    const int* dst0    = (const int*)d_in[2];
    const int* src1    = (const int*)d_in[3];
    const int* dst1    = (const int*)d_in[4];
    const int* pos_src = (const int*)d_in[5];
    const int* pos_dst = (const int*)d_in[6];
    const int* neg_src = (const int*)d_in[7];
    const int* neg_dst = (const int*)d_in[8];
    const float* W0    = (const float*)d_in[9];
    const float* loop0 = (const float*)d_in[10];
    const float* b0    = (const float*)d_in[11];
    const float* W1    = (const float*)d_in[12];
    const float* loop1 = (const float*)d_in[13];
    const float* b1    = (const float*)d_in[14];
    const float* pw1   = (const float*)d_in[15];
    const float* pb1   = (const float*)d_in[16];
    const float* pw2   = (const float*)d_in[17];
    const float* pb2   = (const float*)d_in[18];

    const int E0 = in_sizes[1];
    const int E1 = in_sizes[3];
    const int NP = in_sizes[5];

    float *agg0, *h0, *agg1, *h1;
    cudaGetSymbolAddress((void**)&agg0, g_agg0);
    cudaGetSymbolAddress((void**)&h0,   g_h0);
    cudaGetSymbolAddress((void**)&agg1, g_agg1);
    cudaGetSymbolAddress((void**)&h1,   g_h1);
    int *deg0, *row0, *eidx0, *deg1, *row1, *eidx1, *bsum0, *boff0, *bsum1, *boff1;
    cudaGetSymbolAddress((void**)&deg0,  g_deg0);
    cudaGetSymbolAddress((void**)&row0,  g_row0);
    cudaGetSymbolAddress((void**)&eidx0, g_eidx0);
    cudaGetSymbolAddress((void**)&deg1,  g_deg1);
    cudaGetSymbolAddress((void**)&row1,  g_row1);
    cudaGetSymbolAddress((void**)&eidx1, g_eidx1);
    cudaGetSymbolAddress((void**)&bsum0, g_bsum0);
    cudaGetSymbolAddress((void**)&boff0, g_boff0);
    cudaGetSymbolAddress((void**)&bsum1, g_bsum1);
    cudaGetSymbolAddress((void**)&boff1, g_boff1);

    float* out   = (float*)d_out;
    float* out_h = out + 2 * NP;   // [10000, 256] final embeddings

    // -------- CSR build for both layers (6 launches) --------
    zero_deg_kernel<<<((NDST0 + NDST1) / 4 + 255) / 256, 256>>>(deg0, deg1);
    hist_kernel<<<(E0 + E1 + 255) / 256, 256>>>(dst0, deg0, E0, dst1, deg1, E1);
    block_scan_kernel<<<NB0 + NB1, 1024>>>(deg0, row0, bsum0, deg1, row1, bsum1);
    bsum_scan_kernel<<<2, 32>>>(bsum0, boff0, bsum1, boff1);
    add_off_kernel<<<(NDST0 + NDST1 + 255) / 256, 256>>>(row0, boff0, row1, boff1);
    place_kernel<<<(E0 + E1 + 255) / 256, 256>>>(src0, dst0, row0, eidx0, E0,
                                                 src1, dst1, row1, eidx1, E1);

    // -------- layer 0: fused (loop0 GEMM || gather0) --------
    {
        const int gX = DIM / 128;                       // 2
        const int gY = (NDST0 + 127) / 128;             // 391
        const int gemmBlocks = gX * gY;                 // 782
        const int gatherBlocks = (NDST0 + 7) / 8;       // 6250
        fused_loop_gather_kernel<128, 128, 16, 8, 8>
            <<<gemmBlocks + gatherBlocks, 256>>>(
            NDST0, DIM, x, DIM, loop0, DIM, b0, h0, DIM,
            gemmBlocks, gX,
            x, eidx0, row0, agg0, NDST0);
    }
    // h0 = relu( bdd(agg0, W0) + h0 )
    {
        dim3 grid(1, (NDST0 + 127) / 128, 4);
        bdd_gemm_kernel<128, 64, 16, 8, 4><<<grid, 256>>>(
            NDST0, 64, agg0, DIM, 64, W0, 64, 64 * 64, h0, h0, DIM, 64);
    }

    // -------- layer 1: fused (loop1 GEMM || gather1) --------
    {
        const int gX = DIM / 128;                       // 2
        const int gY = (NDST1 + 127) / 128;             // 79
        const int gemmBlocks = gX * gY;                 // 158
        const int gatherBlocks = (NDST1 + 7) / 8;       // 1250
        fused_loop_gather_kernel<128, 128, 16, 8, 8>
            <<<gemmBlocks + gatherBlocks, 256>>>(
            NDST1, DIM, h0, DIM, loop1, DIM, b1, h1, DIM,
            gemmBlocks, gX,
            h0, eidx1, row1, agg1, NDST1);
    }
    {
        dim3 grid(1, (NDST1 + 127) / 128, 4);
        bdd_gemm_kernel<128, 64, 16, 8, 4><<<grid, 256>>>(
            NDST1, 64, agg1, DIM, 64, W1, 64, 64 * 64, h1, out_h, DIM, 64);
    }

    // prediction head: 10000 pairs -> out[0:10000]
    pred_kernel<<<(2 * NP) / 16, 128>>>(out_h, pos_src, pos_dst, neg_src, neg_dst,
                                        pw1, pb1, pw2, pb2, out, NP);
}